// round 5
// baseline (speedup 1.0000x reference)
#include <cuda_runtime.h>
#include <cuda_bf16.h>
#include <cstdint>

#define N_EL     19
#define N_GRAPHS 1800
#define N_NODES  (N_GRAPHS * N_EL)   // 34200
#define C        128

// fp32 scratch for aggregated features (17.5 MB)
__device__ float g_agg[N_NODES * C];

// ===========================================================================
// helpers
// ===========================================================================
__device__ __forceinline__ uint32_t s2u(const void* p) {
    uint32_t a;
    asm("{ .reg .u64 t; cvta.to.shared.u64 t, %1; cvt.u32.u64 %0, t; }"
        : "=r"(a) : "l"(p));
    return a;
}
__device__ __forceinline__ uint32_t pack2(float a, float b) {
    __nv_bfloat162 t = __floats2bfloat162_rn(a, b);   // a -> low half
    return *reinterpret_cast<uint32_t*>(&t);
}
// split 8 fp32 into bf16 hi plane + bf16 residual plane (2 packed per word)
__device__ __forceinline__ void cvt8(float4 a, float4 b, uint4& hi, uint4& lo) {
    float f[8] = {a.x, a.y, a.z, a.w, b.x, b.y, b.z, b.w};
    float fh[8], fl[8];
#pragma unroll
    for (int i = 0; i < 8; i++) {
        __nv_bfloat16 h = __float2bfloat16_rn(f[i]);
        fh[i] = __bfloat162float(h);
        fl[i] = f[i] - fh[i];
    }
    hi.x = pack2(fh[0], fh[1]); hi.y = pack2(fh[2], fh[3]);
    hi.z = pack2(fh[4], fh[5]); hi.w = pack2(fh[6], fh[7]);
    lo.x = pack2(fl[0], fl[1]); lo.y = pack2(fl[2], fl[3]);
    lo.z = pack2(fl[4], fl[5]); lo.w = pack2(fl[6], fl[7]);
}
__device__ __forceinline__ void sts16(uint32_t addr, uint4 v) {
    asm volatile("st.shared.v4.b32 [%0], {%1,%2,%3,%4};"
                 :: "r"(addr), "r"(v.x), "r"(v.y), "r"(v.z), "r"(v.w) : "memory");
}
__device__ __forceinline__ void ldsm4(uint32_t addr, uint32_t& r0, uint32_t& r1,
                                      uint32_t& r2, uint32_t& r3) {
    asm volatile("ldmatrix.sync.aligned.m8n8.x4.shared.b16 {%0,%1,%2,%3}, [%4];"
                 : "=r"(r0), "=r"(r1), "=r"(r2), "=r"(r3) : "r"(addr));
}
__device__ __forceinline__ void mma16816(float* d, uint32_t a0, uint32_t a1,
                                         uint32_t a2, uint32_t a3,
                                         uint32_t b0, uint32_t b1) {
    asm volatile(
        "mma.sync.aligned.m16n8k16.row.col.f32.bf16.bf16.f32 "
        "{%0,%1,%2,%3}, {%4,%5,%6,%7}, {%8,%9}, {%0,%1,%2,%3};"
        : "+f"(d[0]), "+f"(d[1]), "+f"(d[2]), "+f"(d[3])
        : "r"(a0), "r"(a1), "r"(a2), "r"(a3), "r"(b0), "r"(b1));
}
// 32B rows, XOR-16B swizzle -> conflict-free ldmatrix & 16B-aligned sts
__device__ __forceinline__ uint32_t rowoff(uint32_t r, uint32_t seg) {
    return (r * 32u + seg * 16u) ^ ((r & 4u) << 2);
}

// ===========================================================================
// Kernel 1: per-graph agg = A @ X (fp32). One block/graph, 128 threads.
// ===========================================================================
__global__ __launch_bounds__(128) void agg_kernel(const float* __restrict__ x,
                                                  const float* __restrict__ ew) {
    __shared__ float Xs[N_EL][C];
    __shared__ float A[N_EL][N_EL + 1];

    const int g = blockIdx.x;
    const int c = threadIdx.x;
    const float* xg = x + (size_t)g * N_EL * C;

#pragma unroll
    for (int i = 0; i < N_EL; i++)
        Xs[i][c] = xg[i * C + c];

    for (int e = threadIdx.x; e < N_EL * N_EL; e += blockDim.x) {
        int j = e / N_EL, i = e % N_EL;
        float w = 0.0f;
        if (i != j) {
            int r = (j < i) ? j : (j - 1);
            w = ew[i * (N_EL - 1) + r];
        }
        A[j][i] = w;
    }
    __syncthreads();

    float* aggg = g_agg + (size_t)g * N_EL * C;
#pragma unroll
    for (int j = 0; j < N_EL; j++) {
        float acc = 0.0f;
#pragma unroll
        for (int i = 0; i < N_EL; i++)
            acc = fmaf(A[j][i], Xs[i][c], acc);
        aggg[j * C + c] = acc;
    }
}

// ===========================================================================
// Kernel 2: bf16x3 GEMM via mma.sync
//   out[34200,128] = [agg|x][34200,256] @ [Wrel|Wroot]^T[256,128] + b
// M_CTA=128 x N_CTA=64 per CTA, 256 threads (8 warps: 4m x 2n, 32x32 warp
// tile), 2 CTAs/SM. B (this CTA's 64 cols, all 256 K) staged once; A
// double-buffered in 32-wide K chunks, ONE sync per iter.
// smem (96KB dynamic):
//   [0,32K)    B hi : 16 k16-tiles x (64 rows x 32B = 2KB)
//   [32K,64K)  B lo
//   [64K,96K)  A buf0/buf1 : each 16KB = {hi: 2 tiles x 4KB} {lo at +8KB}
// ===========================================================================
#define M_CTA  128
#define MTILES ((N_NODES + M_CTA - 1) / M_CTA)   // 268
#define GRID2  (MTILES * 2)                       // 536
#define BH_OFF 0
#define BL_OFF 32768
#define A_OFF  65536
#define ABUF   16384
#define SMEM_BYTES 98304

__global__ __launch_bounds__(256, 2) void gemm_mma(const float* __restrict__ x,
                                                   const float* __restrict__ Wrel,
                                                   const float* __restrict__ brel,
                                                   const float* __restrict__ Wroot,
                                                   float* __restrict__ out) {
    extern __shared__ __align__(16) char smem[];
    const uint32_t sb = s2u(smem);

    const int tid   = threadIdx.x;
    const int wid   = tid >> 5;
    const int lane  = tid & 31;
    const int mtile = blockIdx.x >> 1;
    const int nh    = blockIdx.x & 1;    // which 64-col half of output
    const int wm    = wid >> 1;          // 0..3 -> 32-row slab
    const int wn    = wid & 1;           // 0..1 -> 32-col slab

    // ---- stage ALL of B for this n-half once: thread -> (n = tid&63, q = tid>>6)
    {
        const int n = tid & 63, q = tid >> 6;                 // q: 64-wide K quarter
        const int ncol = nh * 64 + n;
        const float* wsrc = ((q < 2) ? Wrel + (size_t)ncol * C + q * 64
                                     : Wroot + (size_t)ncol * C + (q - 2) * 64);
#pragma unroll
        for (int t = 0; t < 4; t++) {                         // 4 k16-tiles / quarter
            const float4* s4 = (const float4*)(wsrc + t * 16);
            uint4 h0, l0, h1, l1;
            cvt8(s4[0], s4[1], h0, l0);                       // k 0-7  (seg 0)
            cvt8(s4[2], s4[3], h1, l1);                       // k 8-15 (seg 1)
            const uint32_t tb = sb + (uint32_t)(q * 4 + t) * 2048u;
            sts16(tb + BH_OFF + rowoff(n, 0), h0);
            sts16(tb + BH_OFF + rowoff(n, 1), h1);
            sts16(tb + BL_OFF + rowoff(n, 0), l0);
            sts16(tb + BL_OFF + rowoff(n, 1), l1);
        }
    }

    // staging identity for A: thread -> (row 0..127, k16-subtile 0/1)
    const int srow  = tid >> 1;
    const int shal  = tid & 1;
    const int growA = mtile * M_CTA + srow;
    const bool avalid = growA < N_NODES;
    const uint32_t a_sts0 = rowoff((uint32_t)srow, 0);
    const uint32_t a_sts1 = rowoff((uint32_t)srow, 1);

    float acc[2][4][4];
#pragma unroll
    for (int m = 0; m < 2; m++)
#pragma unroll
        for (int n = 0; n < 4; n++)
#pragma unroll
            for (int q = 0; q < 4; q++)
                acc[m][n][q] = 0.0f;

    const float4 z4 = make_float4(0.f, 0.f, 0.f, 0.f);
    float4 pa0 = z4, pa1 = z4, pa2 = z4, pa3 = z4;

    // prefetch chunk 0 (k 0..31 of agg): this thread's k16 subtile (16 floats)
    if (avalid) {
        const float4* s4 = (const float4*)(g_agg + (size_t)growA * C + shal * 16);
        pa0 = s4[0]; pa1 = s4[1]; pa2 = s4[2]; pa3 = s4[3];
    }

    // ldmatrix lane addressing (constant per thread)
    const int tt = lane >> 3;
    const int rr = lane & 7;
    // A: row0 = wm*32 + (tt&1)*8 + rr, seg = tt>>1; +m*16 rows = +512B
    const uint32_t a_ld = rowoff((uint32_t)(wm * 32 + (tt & 1) * 8 + rr),
                                 (uint32_t)(tt >> 1));
    // B: n0 = wn*32 + (tt>>1)*8 + rr, seg = tt&1; +p*16 rows = +512B
    const uint32_t b_ld = rowoff((uint32_t)(wn * 32 + (tt >> 1) * 8 + rr),
                                 (uint32_t)(tt & 1));

    for (int i = 0; i < 8; i++) {
        // ---- store prefetched chunk i into buffer i&1 (tile t = shal)
        {
            const uint32_t ab = sb + A_OFF + (uint32_t)(i & 1) * ABUF
                              + (uint32_t)shal * 4096u;
            uint4 h, l;
            cvt8(pa0, pa1, h, l);                 // seg 0 (k 0-7 of subtile)
            sts16(ab + a_sts0, h);
            sts16(ab + 8192u + a_sts0, l);
            cvt8(pa2, pa3, h, l);                 // seg 1 (k 8-15)
            sts16(ab + a_sts1, h);
            sts16(ab + 8192u + a_sts1, l);
        }
        __syncthreads();

        // ---- prefetch chunk i+1 (hidden under MMA below)
        if (i < 7) {
            const int c = i + 1;
            const float* asrc = (c < 4) ? g_agg : x;
            const int col = (c & 3) * 32 + shal * 16;
            if (avalid) {
                const float4* s4 = (const float4*)(asrc + (size_t)growA * C + col);
                pa0 = s4[0]; pa1 = s4[1]; pa2 = s4[2]; pa3 = s4[3];
            } else {
                pa0 = z4; pa1 = z4; pa2 = z4; pa3 = z4;
            }
        }

        // ---- MMA: 2 k16 subtiles of this chunk
        const uint32_t abuf = sb + A_OFF + (uint32_t)(i & 1) * ABUF;
#pragma unroll
        for (int t = 0; t < 2; t++) {
            const uint32_t btile = sb + BH_OFF + (uint32_t)(i * 2 + t) * 2048u;
            uint32_t bh[4][2], bl[4][2];
#pragma unroll
            for (int p = 0; p < 2; p++) {
                uint32_t r0, r1, r2, r3;
                ldsm4(btile + b_ld + (uint32_t)p * 512u, r0, r1, r2, r3);
                bh[p * 2 + 0][0] = r0; bh[p * 2 + 0][1] = r1;
                bh[p * 2 + 1][0] = r2; bh[p * 2 + 1][1] = r3;
                ldsm4(btile + (BL_OFF - BH_OFF) + b_ld + (uint32_t)p * 512u,
                      r0, r1, r2, r3);
                bl[p * 2 + 0][0] = r0; bl[p * 2 + 0][1] = r1;
                bl[p * 2 + 1][0] = r2; bl[p * 2 + 1][1] = r3;
            }
#pragma unroll
            for (int m = 0; m < 2; m++) {
                const uint32_t abase = abuf + (uint32_t)t * 4096u + a_ld
                                     + (uint32_t)m * 512u;
                uint32_t ah0, ah1, ah2, ah3, al0, al1, al2, al3;
                ldsm4(abase, ah0, ah1, ah2, ah3);
                ldsm4(abase + 8192u, al0, al1, al2, al3);
#pragma unroll
                for (int n = 0; n < 4; n++) {
                    mma16816(acc[m][n], ah0, ah1, ah2, ah3, bh[n][0], bh[n][1]);
                    mma16816(acc[m][n], ah0, ah1, ah2, ah3, bl[n][0], bl[n][1]);
                    mma16816(acc[m][n], al0, al1, al2, al3, bh[n][0], bh[n][1]);
                }
            }
        }
        // no trailing sync needed: next iter's start-sync orders buffer reuse
    }

    // ---- epilogue: bias + store (this CTA's 64-col half)
    float bv[4][2];
#pragma unroll
    for (int n = 0; n < 4; n++) {
        const int col = nh * 64 + wn * 32 + n * 8 + (lane & 3) * 2;
        bv[n][0] = brel[col];
        bv[n][1] = brel[col + 1];
    }
#pragma unroll
    for (int m = 0; m < 2; m++) {
        const int grow0 = mtile * M_CTA + wm * 32 + m * 16 + (lane >> 2);
        const int grow1 = grow0 + 8;
#pragma unroll
        for (int n = 0; n < 4; n++) {
            const int col = nh * 64 + wn * 32 + n * 8 + (lane & 3) * 2;
            if (grow0 < N_NODES) {
                float2 v = make_float2(acc[m][n][0] + bv[n][0],
                                       acc[m][n][1] + bv[n][1]);
                *(float2*)(out + (size_t)grow0 * C + col) = v;
            }
            if (grow1 < N_NODES) {
                float2 v = make_float2(acc[m][n][2] + bv[n][0],
                                       acc[m][n][3] + bv[n][1]);
                *(float2*)(out + (size_t)grow1 * C + col) = v;
            }
        }
    }
}

// ===========================================================================
// inputs (metadata order): x, edge_index, edge_weights, W_rel, b_rel, W_root
// ===========================================================================
extern "C" void kernel_launch(void* const* d_in, const int* in_sizes, int n_in,
                              void* d_out, int out_size) {
    const float* x     = (const float*)d_in[0];
    const float* ew    = (const float*)d_in[2];
    const float* Wrel  = (const float*)d_in[3];
    const float* brel  = (const float*)d_in[4];
    const float* Wroot = (const float*)d_in[5];
    float* out = (float*)d_out;

    cudaFuncSetAttribute(gemm_mma, cudaFuncAttributeMaxDynamicSharedMemorySize,
                         SMEM_BYTES);

    agg_kernel<<<N_GRAPHS, 128>>>(x, ew);
    gemm_mma<<<GRID2, 256, SMEM_BYTES>>>(x, Wrel, brel, Wroot, out);
}

// round 6
// speedup vs baseline: 1.1194x; 1.1194x over previous
#include <cuda_runtime.h>
#include <cuda_bf16.h>
#include <cstdint>

#define N_EL     19
#define N_GRAPHS 1800
#define N_NODES  (N_GRAPHS * N_EL)   // 34200
#define C        128

// pre-split bf16 planes (8.75 MB each)
__device__ __nv_bfloat16 g_Ahi[N_NODES * C];
__device__ __nv_bfloat16 g_Alo[N_NODES * C];
__device__ __nv_bfloat16 g_Xhi[N_NODES * C];
__device__ __nv_bfloat16 g_Xlo[N_NODES * C];

// ===========================================================================
// helpers
// ===========================================================================
__device__ __forceinline__ uint32_t s2u(const void* p) {
    uint32_t a;
    asm("{ .reg .u64 t; cvta.to.shared.u64 t, %1; cvt.u32.u64 %0, t; }"
        : "=r"(a) : "l"(p));
    return a;
}
__device__ __forceinline__ uint32_t pack2(float a, float b) {
    __nv_bfloat162 t = __floats2bfloat162_rn(a, b);   // a -> low half
    return *reinterpret_cast<uint32_t*>(&t);
}
// split 8 fp32 into bf16 hi plane + bf16 residual plane (2 packed per word)
__device__ __forceinline__ void cvt8(float4 a, float4 b, uint4& hi, uint4& lo) {
    float f[8] = {a.x, a.y, a.z, a.w, b.x, b.y, b.z, b.w};
    float fh[8], fl[8];
#pragma unroll
    for (int i = 0; i < 8; i++) {
        __nv_bfloat16 h = __float2bfloat16_rn(f[i]);
        fh[i] = __bfloat162float(h);
        fl[i] = f[i] - fh[i];
    }
    hi.x = pack2(fh[0], fh[1]); hi.y = pack2(fh[2], fh[3]);
    hi.z = pack2(fh[4], fh[5]); hi.w = pack2(fh[6], fh[7]);
    lo.x = pack2(fl[0], fl[1]); lo.y = pack2(fl[2], fl[3]);
    lo.z = pack2(fl[4], fl[5]); lo.w = pack2(fl[6], fl[7]);
}
__device__ __forceinline__ void sts16(uint32_t addr, uint4 v) {
    asm volatile("st.shared.v4.b32 [%0], {%1,%2,%3,%4};"
                 :: "r"(addr), "r"(v.x), "r"(v.y), "r"(v.z), "r"(v.w) : "memory");
}
__device__ __forceinline__ void ldsm4(uint32_t addr, uint32_t& r0, uint32_t& r1,
                                      uint32_t& r2, uint32_t& r3) {
    asm volatile("ldmatrix.sync.aligned.m8n8.x4.shared.b16 {%0,%1,%2,%3}, [%4];"
                 : "=r"(r0), "=r"(r1), "=r"(r2), "=r"(r3) : "r"(addr));
}
__device__ __forceinline__ void mma16816(float* d, uint32_t a0, uint32_t a1,
                                         uint32_t a2, uint32_t a3,
                                         uint32_t b0, uint32_t b1) {
    asm volatile(
        "mma.sync.aligned.m16n8k16.row.col.f32.bf16.bf16.f32 "
        "{%0,%1,%2,%3}, {%4,%5,%6,%7}, {%8,%9}, {%0,%1,%2,%3};"
        : "+f"(d[0]), "+f"(d[1]), "+f"(d[2]), "+f"(d[3])
        : "r"(a0), "r"(a1), "r"(a2), "r"(a3), "r"(b0), "r"(b1));
}
// 32B rows, XOR-16B swizzle -> conflict-free ldmatrix & 16B-aligned st/cp
__device__ __forceinline__ uint32_t rowoff(uint32_t r, uint32_t seg) {
    return (r * 32u + seg * 16u) ^ ((r & 4u) << 2);
}
__device__ __forceinline__ void cpa16(uint32_t dst, const void* src, uint32_t sz) {
    asm volatile("cp.async.cg.shared.global [%0], [%1], 16, %2;"
                 :: "r"(dst), "l"(src), "r"(sz) : "memory");
}
#define CP_COMMIT() asm volatile("cp.async.commit_group;" ::: "memory")
#define CP_WAIT1()  asm volatile("cp.async.wait_group 1;" ::: "memory")

// ===========================================================================
// Kernel 1: per-graph agg = A @ X, emit bf16 hi/lo planes for agg AND x.
// One block/graph, 128 threads (thread = channel).
// ===========================================================================
__global__ __launch_bounds__(128) void agg_kernel(const float* __restrict__ x,
                                                  const float* __restrict__ ew) {
    __shared__ float Xs[N_EL][C];
    __shared__ float A[N_EL][N_EL + 1];

    const int g = blockIdx.x;
    const int c = threadIdx.x;
    const float* xg = x + (size_t)g * N_EL * C;

#pragma unroll
    for (int i = 0; i < N_EL; i++)
        Xs[i][c] = xg[i * C + c];

    for (int e = threadIdx.x; e < N_EL * N_EL; e += blockDim.x) {
        int j = e / N_EL, i = e % N_EL;
        float w = 0.0f;
        if (i != j) {
            int r = (j < i) ? j : (j - 1);
            w = ew[i * (N_EL - 1) + r];
        }
        A[j][i] = w;
    }
    __syncthreads();

    const size_t base = (size_t)g * N_EL * C + c;
#pragma unroll
    for (int i = 0; i < N_EL; i++) {            // x planes (from smem, free read)
        float v = Xs[i][c];
        __nv_bfloat16 h = __float2bfloat16_rn(v);
        g_Xhi[base + (size_t)i * C] = h;
        g_Xlo[base + (size_t)i * C] = __float2bfloat16_rn(v - __bfloat162float(h));
    }
#pragma unroll
    for (int j = 0; j < N_EL; j++) {            // agg rows + planes
        float acc = 0.0f;
#pragma unroll
        for (int i = 0; i < N_EL; i++)
            acc = fmaf(A[j][i], Xs[i][c], acc);
        __nv_bfloat16 h = __float2bfloat16_rn(acc);
        g_Ahi[base + (size_t)j * C] = h;
        g_Alo[base + (size_t)j * C] = __float2bfloat16_rn(acc - __bfloat162float(h));
    }
}

// ===========================================================================
// Kernel 2: bf16x3 GEMM via mma.sync, cp.async-fed A ring.
//   out[34200,128] = [agg|x][34200,256] @ [Wrel|Wroot]^T[256,128] + b
// M_CTA=256, 512 thr (16 warps, 4x4 warp grid), grid=134 (1 wave).
// smem (224KB dynamic):
//   [0,64K)     B hi : 16 k16-tiles x (128 rows x 32B = 4KB)
//   [64K,128K)  B lo
//   [128K,224K) A ring: 3 slots x 32KB; slot = k32 stage =
//               {t0_hi 8K}{t1_hi 8K}{t0_lo 8K}{t1_lo 8K}
// 8 k32 stages: 0..3 from agg planes, 4..7 from x planes.
// ===========================================================================
#define M_CTA  256
#define GRID2  ((N_NODES + M_CTA - 1) / M_CTA)   // 134
#define BH_OFF 0
#define BL_OFF 65536
#define A_OFF  131072
#define SLOT   32768
#define SMEM_BYTES 229376

__global__ __launch_bounds__(512) void gemm_mma(const float* __restrict__ Wrel,
                                                const float* __restrict__ brel,
                                                const float* __restrict__ Wroot,
                                                float* __restrict__ out) {
    extern __shared__ __align__(16) char smem[];
    const uint32_t sb = s2u(smem);

    const int tid  = threadIdx.x;
    const int wid  = tid >> 5;
    const int lane = tid & 31;
    const int cta  = blockIdx.x;
    const int wm   = wid >> 2;
    const int wn   = wid & 3;

    // per-thread cp.async identity: (row, 16B seg of a k16 tile)
    const int arow  = tid >> 1;          // 0..255
    const int aseg  = tid & 1;           // 0/1
    const int growA = cta * M_CTA + arow;
    const uint32_t asz = (growA < N_NODES) ? 16u : 0u;
    const size_t abase = (growA < N_NODES) ? (size_t)growA * C : 0;
    const uint32_t a_dst = rowoff((uint32_t)arow, (uint32_t)aseg);

    // ---- issue stages 0,1 (agg planes)
#pragma unroll
    for (int s = 0; s < 2; s++) {
        const uint32_t st = sb + A_OFF + (uint32_t)s * SLOT;
        const size_t col = (size_t)(s * 32) + aseg * 8;
#pragma unroll
        for (int t = 0; t < 2; t++) {
            cpa16(st + (uint32_t)t * 8192u + a_dst,           g_Ahi + abase + col + t * 16, asz);
            cpa16(st + 16384u + (uint32_t)t * 8192u + a_dst,  g_Alo + abase + col + t * 16, asz);
        }
        CP_COMMIT();
    }

    // ---- stage ALL of B once (register convert from fp32 weights)
    {
        const int n = tid & 127, q = tid >> 7;               // q: 64-wide K quarter
        const float* wsrc = ((q < 2) ? Wrel + (size_t)n * C + q * 64
                                     : Wroot + (size_t)n * C + (q - 2) * 64);
#pragma unroll
        for (int t = 0; t < 4; t++) {
            const float4* s4 = (const float4*)(wsrc + t * 16);
            uint4 h0, l0, h1, l1;
            cvt8(s4[0], s4[1], h0, l0);
            cvt8(s4[2], s4[3], h1, l1);
            const uint32_t tb = sb + (uint32_t)(q * 4 + t) * 4096u;
            sts16(tb + BH_OFF + rowoff(n, 0), h0);
            sts16(tb + BH_OFF + rowoff(n, 1), h1);
            sts16(tb + BL_OFF + rowoff(n, 0), l0);
            sts16(tb + BL_OFF + rowoff(n, 1), l1);
        }
    }

    float acc[4][4][4];
#pragma unroll
    for (int m = 0; m < 4; m++)
#pragma unroll
        for (int n = 0; n < 4; n++)
#pragma unroll
            for (int q = 0; q < 4; q++)
                acc[m][n][q] = 0.0f;

    // ldmatrix lane addressing
    const int tt = lane >> 3;
    const int rr = lane & 7;
    const uint32_t a_ld = rowoff((uint32_t)(wm * 64 + (tt & 1) * 8 + rr),
                                 (uint32_t)(tt >> 1));
    const uint32_t b_ld = rowoff((uint32_t)(wn * 32 + (tt >> 1) * 8 + rr),
                                 (uint32_t)(tt & 1));

#pragma unroll 1
    for (int i = 0; i < 8; i++) {
        CP_WAIT1();            // stage i complete (outstanding: {i, i+1})
        __syncthreads();       // visibility + slot (i+2)%3 reads done

        // issue stage i+2 into slot (i+2)%3 (empty commit keeps group count)
        if (i + 2 < 8) {
            const int s = i + 2;
            const uint32_t st = sb + A_OFF + (uint32_t)(s % 3) * SLOT;
            const __nv_bfloat16* hs = (s < 4) ? g_Ahi : g_Xhi;
            const __nv_bfloat16* ls = (s < 4) ? g_Alo : g_Xlo;
            const size_t col = (size_t)((s & 3) * 32) + aseg * 8;
#pragma unroll
            for (int t = 0; t < 2; t++) {
                cpa16(st + (uint32_t)t * 8192u + a_dst,          hs + abase + col + t * 16, asz);
                cpa16(st + 16384u + (uint32_t)t * 8192u + a_dst, ls + abase + col + t * 16, asz);
            }
        }
        CP_COMMIT();

        // ---- MMA on slot i%3 (2 k16 tiles)
        const uint32_t abuf = sb + A_OFF + (uint32_t)(i % 3) * SLOT;
#pragma unroll
        for (int t = 0; t < 2; t++) {
            const uint32_t btile = sb + BH_OFF + (uint32_t)(i * 2 + t) * 4096u;
            uint32_t bh[4][2], bl[4][2];
#pragma unroll
            for (int p = 0; p < 2; p++) {
                uint32_t r0, r1, r2, r3;
                ldsm4(btile + b_ld + (uint32_t)p * 512u, r0, r1, r2, r3);
                bh[p * 2 + 0][0] = r0; bh[p * 2 + 0][1] = r1;
                bh[p * 2 + 1][0] = r2; bh[p * 2 + 1][1] = r3;
                ldsm4(btile + (BL_OFF - BH_OFF) + b_ld + (uint32_t)p * 512u,
                      r0, r1, r2, r3);
                bl[p * 2 + 0][0] = r0; bl[p * 2 + 0][1] = r1;
                bl[p * 2 + 1][0] = r2; bl[p * 2 + 1][1] = r3;
            }
#pragma unroll
            for (int m = 0; m < 4; m++) {
                const uint32_t ab = abuf + (uint32_t)t * 8192u + a_ld
                                  + (uint32_t)m * 512u;
                uint32_t ah0, ah1, ah2, ah3, al0, al1, al2, al3;
                ldsm4(ab, ah0, ah1, ah2, ah3);
                ldsm4(ab + 16384u, al0, al1, al2, al3);
#pragma unroll
                for (int n = 0; n < 4; n++) {
                    mma16816(acc[m][n], ah0, ah1, ah2, ah3, bh[n][0], bh[n][1]);
                    mma16816(acc[m][n], ah0, ah1, ah2, ah3, bl[n][0], bl[n][1]);
                    mma16816(acc[m][n], al0, al1, al2, al3, bh[n][0], bh[n][1]);
                }
            }
        }
    }

    // ---- epilogue: bias + store
    float bv[4][2];
#pragma unroll
    for (int n = 0; n < 4; n++) {
        const int col = wn * 32 + n * 8 + (lane & 3) * 2;
        bv[n][0] = brel[col];
        bv[n][1] = brel[col + 1];
    }
#pragma unroll
    for (int m = 0; m < 4; m++) {
        const int grow0 = cta * M_CTA + wm * 64 + m * 16 + (lane >> 2);
        const int grow1 = grow0 + 8;
#pragma unroll
        for (int n = 0; n < 4; n++) {
            const int col = wn * 32 + n * 8 + (lane & 3) * 2;
            if (grow0 < N_NODES) {
                float2 v = make_float2(acc[m][n][0] + bv[n][0],
                                       acc[m][n][1] + bv[n][1]);
                *(float2*)(out + (size_t)grow0 * C + col) = v;
            }
            if (grow1 < N_NODES) {
                float2 v = make_float2(acc[m][n][2] + bv[n][0],
                                       acc[m][n][3] + bv[n][1]);
                *(float2*)(out + (size_t)grow1 * C + col) = v;
            }
        }
    }
}

// ===========================================================================
// inputs (metadata order): x, edge_index, edge_weights, W_rel, b_rel, W_root
// ===========================================================================
extern "C" void kernel_launch(void* const* d_in, const int* in_sizes, int n_in,
                              void* d_out, int out_size) {
    const float* x     = (const float*)d_in[0];
    const float* ew    = (const float*)d_in[2];
    const float* Wrel  = (const float*)d_in[3];
    const float* brel  = (const float*)d_in[4];
    const float* Wroot = (const float*)d_in[5];
    float* out = (float*)d_out;

    cudaFuncSetAttribute(gemm_mma, cudaFuncAttributeMaxDynamicSharedMemorySize,
                         SMEM_BYTES);

    agg_kernel<<<N_GRAPHS, 128>>>(x, ew);
    gemm_mma<<<GRID2, 512, SMEM_BYTES>>>(Wrel, brel, Wroot, out);
}

// round 7
// speedup vs baseline: 1.1718x; 1.0468x over previous
#include <cuda_runtime.h>
#include <cuda_bf16.h>
#include <cstdint>

#define N_EL     19
#define N_GRAPHS 1800
#define N_NODES  (N_GRAPHS * N_EL)   // 34200
#define C        128

// fp32 scratch for aggregated features (17.5 MB)
__device__ float g_agg[N_NODES * C];

// ===========================================================================
// helpers
// ===========================================================================
__device__ __forceinline__ uint32_t s2u(const void* p) {
    uint32_t a;
    asm("{ .reg .u64 t; cvta.to.shared.u64 t, %1; cvt.u32.u64 %0, t; }"
        : "=r"(a) : "l"(p));
    return a;
}
__device__ __forceinline__ uint32_t t32(float f) {   // fp32 -> tf32 (round nearest)
    uint32_t u;
    asm("cvt.rna.tf32.f32 %0, %1;" : "=r"(u) : "f"(f));
    return u;
}
__device__ __forceinline__ void sts16(uint32_t addr, uint4 v) {
    asm volatile("st.shared.v4.b32 [%0], {%1,%2,%3,%4};"
                 :: "r"(addr), "r"(v.x), "r"(v.y), "r"(v.z), "r"(v.w) : "memory");
}
__device__ __forceinline__ uint4 lds16(uint32_t addr) {
    uint4 v;
    asm volatile("ld.shared.v4.b32 {%0,%1,%2,%3}, [%4];"
                 : "=r"(v.x), "=r"(v.y), "=r"(v.z), "=r"(v.w) : "r"(addr));
    return v;
}
__device__ __forceinline__ void mma_tf32(float* d, uint32_t a0, uint32_t a1,
                                         uint32_t a2, uint32_t a3,
                                         uint32_t b0, uint32_t b1) {
    asm volatile(
        "mma.sync.aligned.m16n8k8.row.col.f32.tf32.tf32.f32 "
        "{%0,%1,%2,%3}, {%4,%5,%6,%7}, {%8,%9}, {%0,%1,%2,%3};"
        : "+f"(d[0]), "+f"(d[1]), "+f"(d[2]), "+f"(d[3])
        : "r"(a0), "r"(a1), "r"(a2), "r"(a3), "r"(b0), "r"(b1));
}

// ===========================================================================
// Kernel 1: per-graph agg = A @ X (fp32). One block/graph, 128 threads.
// ===========================================================================
__global__ __launch_bounds__(128) void agg_kernel(const float* __restrict__ x,
                                                  const float* __restrict__ ew) {
    __shared__ float Xs[N_EL][C];
    __shared__ float A[N_EL][N_EL + 1];

    const int g = blockIdx.x;
    const int c = threadIdx.x;
    const float* xg = x + (size_t)g * N_EL * C;

#pragma unroll
    for (int i = 0; i < N_EL; i++)
        Xs[i][c] = xg[i * C + c];

    for (int e = threadIdx.x; e < N_EL * N_EL; e += blockDim.x) {
        int j = e / N_EL, i = e % N_EL;
        float w = 0.0f;
        if (i != j) {
            int r = (j < i) ? j : (j - 1);
            w = ew[i * (N_EL - 1) + r];
        }
        A[j][i] = w;
    }
    __syncthreads();

    float* aggg = g_agg + (size_t)g * N_EL * C;
#pragma unroll
    for (int j = 0; j < N_EL; j++) {
        float acc = 0.0f;
#pragma unroll
        for (int i = 0; i < N_EL; i++)
            acc = fmaf(A[j][i], Xs[i][c], acc);
        aggg[j * C + c] = acc;
    }
}

// ===========================================================================
// Kernel 2: single-product tf32 GEMM via mma.sync.m16n8k8
//   out[34200,128] = [agg|x][34200,256] @ [Wrel|Wroot]^T[256,128] + b
// M_CTA=256, 512 thr (16 warps, 4m x 4n grid, 64x32 warp tile), grid=134.
// smem layout uses k-interleaved rows: within a k32 chunk, element k sits at
// word (k&3)*8 + (k>>2); row stride 36 words. This makes every MMA fragment
// load a 16B-aligned LDS.128 at the bank-conflict floor.
//   [0, 147456)        B: 8 chunks x (128 n-rows x 144B)
//   [147456, 221184)   A: 2 buffers x (256 rows x 144B)
// ===========================================================================
#define M_CTA  256
#define GRID2  ((N_NODES + M_CTA - 1) / M_CTA)   // 134
#define ASTR   36                                 // words per row
#define BCH    18432                              // bytes per B k32 chunk
#define B_OFF  0
#define A_OFF  147456
#define ABUF   36864
#define SMEM_BYTES 221184

__global__ __launch_bounds__(512) void gemm_tf32(const float* __restrict__ x,
                                                 const float* __restrict__ Wrel,
                                                 const float* __restrict__ brel,
                                                 const float* __restrict__ Wroot,
                                                 float* __restrict__ out) {
    extern __shared__ __align__(16) char smem[];
    const uint32_t sb = s2u(smem);

    const int tid  = threadIdx.x;
    const int wid  = tid >> 5;
    const int lane = tid & 31;
    const int cta  = blockIdx.x;
    const int wm   = wid >> 2;
    const int wn   = wid & 3;

    // ---- stage ALL of B once: thread -> (n = tid&127, q = tid>>7 : 64-k quarter)
    {
        const int n = tid & 127, q = tid >> 7;
        const float* wsrc = (q < 2) ? Wrel + (size_t)n * C + q * 64
                                    : Wroot + (size_t)n * C + (q - 2) * 64;
#pragma unroll
        for (int t = 0; t < 4; t++) {                 // k16 blocks in this quarter
            const int kg    = q * 64 + t * 16;
            const int chunk = kg >> 5;
            const int h     = (kg >> 4) & 1;
            const float4* s4 = (const float4*)(wsrc + t * 16);
            float f[16];
            *(float4*)&f[0]  = s4[0];
            *(float4*)&f[4]  = s4[1];
            *(float4*)&f[8]  = s4[2];
            *(float4*)&f[12] = s4[3];
            const uint32_t base = sb + B_OFF + (uint32_t)chunk * BCH
                                + (uint32_t)(n * ASTR + h * 4) * 4u;
#pragma unroll
            for (int cc = 0; cc < 4; cc++) {
                uint4 v = make_uint4(t32(f[cc]), t32(f[cc + 4]),
                                     t32(f[cc + 8]), t32(f[cc + 12]));
                sts16(base + (uint32_t)(cc * 8) * 4u, v);
            }
        }
    }

    // A staging identity: thread -> (row 0..255, k16 half of the 32-chunk)
    const int srow  = tid >> 1;
    const int shal  = tid & 1;
    const int growA = cta * M_CTA + srow;
    const bool avalid = growA < N_NODES;
    const uint32_t a_sts = (uint32_t)(srow * ASTR + shal * 4) * 4u;

    float acc[4][4][4];
#pragma unroll
    for (int m = 0; m < 4; m++)
#pragma unroll
        for (int n = 0; n < 4; n++)
#pragma unroll
            for (int q = 0; q < 4; q++)
                acc[m][n][q] = 0.0f;

    const float4 z4 = make_float4(0.f, 0.f, 0.f, 0.f);
    float pa[16];

    // prefetch chunk 0 (agg k 0..31, this thread's k16 half)
    {
        float4 v0 = z4, v1 = z4, v2 = z4, v3 = z4;
        if (avalid) {
            const float4* s4 = (const float4*)(g_agg + (size_t)growA * C + shal * 16);
            v0 = s4[0]; v1 = s4[1]; v2 = s4[2]; v3 = s4[3];
        }
        *(float4*)&pa[0] = v0; *(float4*)&pa[4] = v1;
        *(float4*)&pa[8] = v2; *(float4*)&pa[12] = v3;
    }

    // fragment lane addressing
    const int fr = lane >> 2;           // 0..7
    const int fc = lane & 3;            // 0..3

#pragma unroll 1
    for (int i = 0; i < 8; i++) {
        // ---- store prefetched chunk i into buffer i&1 (k-interleaved)
        {
            const uint32_t ab = sb + A_OFF + (uint32_t)(i & 1) * ABUF + a_sts;
#pragma unroll
            for (int cc = 0; cc < 4; cc++) {
                uint4 v = make_uint4(t32(pa[cc]), t32(pa[cc + 4]),
                                     t32(pa[cc + 8]), t32(pa[cc + 12]));
                sts16(ab + (uint32_t)(cc * 8) * 4u, v);
            }
        }
        __syncthreads();

        // ---- prefetch chunk i+1 (hidden under MMA)
        if (i < 7) {
            const int nc = i + 1;
            const float* asrc = (nc < 4) ? g_agg : x;
            const int col = (nc & 3) * 32 + shal * 16;
            float4 v0 = z4, v1 = z4, v2 = z4, v3 = z4;
            if (avalid) {
                const float4* s4 = (const float4*)(asrc + (size_t)growA * C + col);
                v0 = s4[0]; v1 = s4[1]; v2 = s4[2]; v3 = s4[3];
            }
            *(float4*)&pa[0] = v0; *(float4*)&pa[4] = v1;
            *(float4*)&pa[8] = v2; *(float4*)&pa[12] = v3;
        }

        // ---- MMA on buffer i&1 against B chunk i
        const uint32_t abuf = sb + A_OFF + (uint32_t)(i & 1) * ABUF;
        const uint32_t bch  = sb + B_OFF + (uint32_t)i * BCH;
#pragma unroll
        for (int s = 0; s < 2; s++) {                 // k16 half (t-pair)
            uint4 bf[4];
#pragma unroll
            for (int n = 0; n < 4; n++)
                bf[n] = lds16(bch + (uint32_t)((wn * 32 + n * 8 + fr) * ASTR
                                               + fc * 8 + 4 * s) * 4u);
#pragma unroll
            for (int m = 0; m < 4; m++) {
                const int row = wm * 64 + m * 16 + fr;
                uint4 lo = lds16(abuf + (uint32_t)(row * ASTR + fc * 8 + 4 * s) * 4u);
                uint4 hi = lds16(abuf + (uint32_t)((row + 8) * ASTR + fc * 8 + 4 * s) * 4u);
#pragma unroll
                for (int n = 0; n < 4; n++)
                    mma_tf32(acc[m][n], lo.x, hi.x, lo.y, hi.y, bf[n].x, bf[n].y);
#pragma unroll
                for (int n = 0; n < 4; n++)
                    mma_tf32(acc[m][n], lo.z, hi.z, lo.w, hi.w, bf[n].z, bf[n].w);
            }
        }
        // single sync per iter: next iter's start-sync orders buffer reuse
    }

    // ---- epilogue: bias + store
    float bv[4][2];
#pragma unroll
    for (int n = 0; n < 4; n++) {
        const int col = wn * 32 + n * 8 + (lane & 3) * 2;
        bv[n][0] = brel[col];
        bv[n][1] = brel[col + 1];
    }
#pragma unroll
    for (int m = 0; m < 4; m++) {
        const int grow0 = cta * M_CTA + wm * 64 + m * 16 + (lane >> 2);
        const int grow1 = grow0 + 8;
#pragma unroll
        for (int n = 0; n < 4; n++) {
            const int col = wn * 32 + n * 8 + (lane & 3) * 2;
            if (grow0 < N_NODES) {
                float2 v = make_float2(acc[m][n][0] + bv[n][0],
                                       acc[m][n][1] + bv[n][1]);
                *(float2*)(out + (size_t)grow0 * C + col) = v;
            }
            if (grow1 < N_NODES) {
                float2 v = make_float2(acc[m][n][2] + bv[n][0],
                                       acc[m][n][3] + bv[n][1]);
                *(float2*)(out + (size_t)grow1 * C + col) = v;
            }
        }
    }
}

// ===========================================================================
// inputs (metadata order): x, edge_index, edge_weights, W_rel, b_rel, W_root
// ===========================================================================
extern "C" void kernel_launch(void* const* d_in, const int* in_sizes, int n_in,
                              void* d_out, int out_size) {
    const float* x     = (const float*)d_in[0];
    const float* ew    = (const float*)d_in[2];
    const float* Wrel  = (const float*)d_in[3];
    const float* brel  = (const float*)d_in[4];
    const float* Wroot = (const float*)d_in[5];
    float* out = (float*)d_out;

    cudaFuncSetAttribute(gemm_tf32, cudaFuncAttributeMaxDynamicSharedMemorySize,
                         SMEM_BYTES);

    agg_kernel<<<N_GRAPHS, 128>>>(x, ew);
    gemm_tf32<<<GRID2, 512, SMEM_BYTES>>>(x, Wrel, brel, Wroot, out);
}

// round 8
// speedup vs baseline: 1.1795x; 1.0066x over previous
#include <cuda_runtime.h>
#include <cuda_bf16.h>
#include <cstdint>

#define N_EL     19
#define N_GRAPHS 1800
#define N_NODES  (N_GRAPHS * N_EL)   // 34200
#define C        128

// fp32 scratch for aggregated features (17.5 MB)
__device__ float g_agg[N_NODES * C];

// ===========================================================================
// helpers
// ===========================================================================
__device__ __forceinline__ uint32_t s2u(const void* p) {
    uint32_t a;
    asm("{ .reg .u64 t; cvta.to.shared.u64 t, %1; cvt.u32.u64 %0, t; }"
        : "=r"(a) : "l"(p));
    return a;
}
__device__ __forceinline__ uint32_t t32(float f) {   // fp32 -> tf32 (round nearest)
    uint32_t u;
    asm("cvt.rna.tf32.f32 %0, %1;" : "=r"(u) : "f"(f));
    return u;
}
__device__ __forceinline__ void sts16(uint32_t addr, uint4 v) {
    asm volatile("st.shared.v4.b32 [%0], {%1,%2,%3,%4};"
                 :: "r"(addr), "r"(v.x), "r"(v.y), "r"(v.z), "r"(v.w) : "memory");
}
__device__ __forceinline__ uint4 lds16(uint32_t addr) {
    uint4 v;
    asm volatile("ld.shared.v4.b32 {%0,%1,%2,%3}, [%4];"
                 : "=r"(v.x), "=r"(v.y), "=r"(v.z), "=r"(v.w) : "r"(addr));
    return v;
}
__device__ __forceinline__ void mma_tf32(float* d, uint32_t a0, uint32_t a1,
                                         uint32_t a2, uint32_t a3,
                                         uint32_t b0, uint32_t b1) {
    asm volatile(
        "mma.sync.aligned.m16n8k8.row.col.f32.tf32.tf32.f32 "
        "{%0,%1,%2,%3}, {%4,%5,%6,%7}, {%8,%9}, {%0,%1,%2,%3};"
        : "+f"(d[0]), "+f"(d[1]), "+f"(d[2]), "+f"(d[3])
        : "r"(a0), "r"(a1), "r"(a2), "r"(a3), "r"(b0), "r"(b1));
}

// ===========================================================================
// Kernel 1: per-graph agg = A @ X (fp32). One block/graph, 128 threads.
// ===========================================================================
__global__ __launch_bounds__(128) void agg_kernel(const float* __restrict__ x,
                                                  const float* __restrict__ ew) {
    __shared__ float Xs[N_EL][C];
    __shared__ float A[N_EL][N_EL + 1];

    const int g = blockIdx.x;
    const int c = threadIdx.x;
    const float* xg = x + (size_t)g * N_EL * C;

#pragma unroll
    for (int i = 0; i < N_EL; i++)
        Xs[i][c] = xg[i * C + c];

    for (int e = threadIdx.x; e < N_EL * N_EL; e += blockDim.x) {
        int j = e / N_EL, i = e % N_EL;
        float w = 0.0f;
        if (i != j) {
            int r = (j < i) ? j : (j - 1);
            w = ew[i * (N_EL - 1) + r];
        }
        A[j][i] = w;
    }
    __syncthreads();

    float* aggg = g_agg + (size_t)g * N_EL * C;
#pragma unroll
    for (int j = 0; j < N_EL; j++) {
        float acc = 0.0f;
#pragma unroll
        for (int i = 0; i < N_EL; i++)
            acc = fmaf(A[j][i], Xs[i][c], acc);
        aggg[j * C + c] = acc;
    }
}

// ===========================================================================
// Kernel 2: single-product tf32 GEMM via mma.sync.m16n8k8
//   out[34200,128] = [agg|x][34200,256] @ [Wrel|Wroot]^T[256,128] + b
// M_CTA=128, 256 thr (8 warps, 2m x 4n grid, 64x32 warp tile), grid=268.
// launch_bounds(256,1): 255-reg budget -> no spills (R3-R7 were capped @128).
// k-interleaved smem rows: within a k32 chunk, element k sits at word
// (k&3)*8 + (k>>2); row stride 36 words -> all fragments are LDS.128.
//   [0, 147456)        B: 8 chunks x (128 n-rows x 144B)
//   [147456, 184320)   A: 2 buffers x (128 rows x 144B)
// ===========================================================================
#define M_CTA  128
#define GRID2  ((N_NODES + M_CTA - 1) / M_CTA)   // 268
#define ASTR   36                                 // words per row
#define BCH    18432                              // bytes per B k32 chunk
#define B_OFF  0
#define A_OFF  147456
#define ABUF   18432
#define SMEM_BYTES 184320

__global__ __launch_bounds__(256, 1) void gemm_tf32(const float* __restrict__ x,
                                                    const float* __restrict__ Wrel,
                                                    const float* __restrict__ brel,
                                                    const float* __restrict__ Wroot,
                                                    float* __restrict__ out) {
    extern __shared__ __align__(16) char smem[];
    const uint32_t sb = s2u(smem);

    const int tid  = threadIdx.x;
    const int wid  = tid >> 5;
    const int lane = tid & 31;
    const int cta  = blockIdx.x;
    const int wm   = wid >> 2;          // 0..1 -> 64-row slab
    const int wn   = wid & 3;           // 0..3 -> 32-col slab

    // ---- stage ALL of B once: thread -> (n = tid&127, q = tid>>7 : K half)
    {
        const int n = tid & 127, q = tid >> 7;       // q=0: Wrel(k0..127), q=1: Wroot
        const float* wsrc = (q == 0) ? Wrel + (size_t)n * C
                                     : Wroot + (size_t)n * C;
#pragma unroll
        for (int t = 0; t < 8; t++) {                // 8 k16 blocks in this half
            const int kg    = q * 128 + t * 16;
            const int chunk = kg >> 5;
            const int h     = (kg >> 4) & 1;
            const float4* s4 = (const float4*)(wsrc + t * 16);
            float f[16];
            *(float4*)&f[0]  = s4[0];
            *(float4*)&f[4]  = s4[1];
            *(float4*)&f[8]  = s4[2];
            *(float4*)&f[12] = s4[3];
            const uint32_t base = sb + B_OFF + (uint32_t)chunk * BCH
                                + (uint32_t)(n * ASTR + h * 4) * 4u;
#pragma unroll
            for (int cc = 0; cc < 4; cc++) {
                uint4 v = make_uint4(t32(f[cc]), t32(f[cc + 4]),
                                     t32(f[cc + 8]), t32(f[cc + 12]));
                sts16(base + (uint32_t)(cc * 8) * 4u, v);
            }
        }
    }

    // A staging identity: thread -> (row 0..127, k16 half of the 32-chunk)
    const int srow  = tid >> 1;
    const int shal  = tid & 1;
    const int growA = cta * M_CTA + srow;
    const bool avalid = growA < N_NODES;
    const uint32_t a_sts = (uint32_t)(srow * ASTR + shal * 4) * 4u;

    float acc[4][4][4];
#pragma unroll
    for (int m = 0; m < 4; m++)
#pragma unroll
        for (int n = 0; n < 4; n++)
#pragma unroll
            for (int q = 0; q < 4; q++)
                acc[m][n][q] = 0.0f;

    const float4 z4 = make_float4(0.f, 0.f, 0.f, 0.f);
    float pa[16];

    // prefetch chunk 0 (agg k 0..31, this thread's k16 half)
    {
        float4 v0 = z4, v1 = z4, v2 = z4, v3 = z4;
        if (avalid) {
            const float4* s4 = (const float4*)(g_agg + (size_t)growA * C + shal * 16);
            v0 = s4[0]; v1 = s4[1]; v2 = s4[2]; v3 = s4[3];
        }
        *(float4*)&pa[0] = v0; *(float4*)&pa[4] = v1;
        *(float4*)&pa[8] = v2; *(float4*)&pa[12] = v3;
    }

    // fragment lane addressing
    const int fr = lane >> 2;           // 0..7
    const int fc = lane & 3;            // 0..3

#pragma unroll 1
    for (int i = 0; i < 8; i++) {
        // ---- store prefetched chunk i into buffer i&1 (k-interleaved)
        {
            const uint32_t ab = sb + A_OFF + (uint32_t)(i & 1) * ABUF + a_sts;
#pragma unroll
            for (int cc = 0; cc < 4; cc++) {
                uint4 v = make_uint4(t32(pa[cc]), t32(pa[cc + 4]),
                                     t32(pa[cc + 8]), t32(pa[cc + 12]));
                sts16(ab + (uint32_t)(cc * 8) * 4u, v);
            }
        }
        __syncthreads();

        // ---- prefetch chunk i+1 (hidden under MMA)
        if (i < 7) {
            const int nc = i + 1;
            const float* asrc = (nc < 4) ? g_agg : x;
            const int col = (nc & 3) * 32 + shal * 16;
            float4 v0 = z4, v1 = z4, v2 = z4, v3 = z4;
            if (avalid) {
                const float4* s4 = (const float4*)(asrc + (size_t)growA * C + col);
                v0 = s4[0]; v1 = s4[1]; v2 = s4[2]; v3 = s4[3];
            }
            *(float4*)&pa[0] = v0; *(float4*)&pa[4] = v1;
            *(float4*)&pa[8] = v2; *(float4*)&pa[12] = v3;
        }

        // ---- MMA on buffer i&1 against B chunk i
        const uint32_t abuf = sb + A_OFF + (uint32_t)(i & 1) * ABUF;
        const uint32_t bch  = sb + B_OFF + (uint32_t)i * BCH;
#pragma unroll
        for (int s = 0; s < 2; s++) {                 // k16 half
            uint4 bf[4];
#pragma unroll
            for (int n = 0; n < 4; n++)
                bf[n] = lds16(bch + (uint32_t)((wn * 32 + n * 8 + fr) * ASTR
                                               + fc * 8 + 4 * s) * 4u);
#pragma unroll
            for (int m = 0; m < 4; m++) {
                const int row = wm * 64 + m * 16 + fr;
                uint4 lo = lds16(abuf + (uint32_t)(row * ASTR + fc * 8 + 4 * s) * 4u);
                uint4 hi = lds16(abuf + (uint32_t)((row + 8) * ASTR + fc * 8 + 4 * s) * 4u);
#pragma unroll
                for (int n = 0; n < 4; n++)
                    mma_tf32(acc[m][n], lo.x, hi.x, lo.y, hi.y, bf[n].x, bf[n].y);
#pragma unroll
                for (int n = 0; n < 4; n++)
                    mma_tf32(acc[m][n], lo.z, hi.z, lo.w, hi.w, bf[n].z, bf[n].w);
            }
        }
        // single sync per iter: next iter's start-sync orders buffer reuse
    }

    // ---- epilogue: bias + store
    float bv[4][2];
#pragma unroll
    for (int n = 0; n < 4; n++) {
        const int col = wn * 32 + n * 8 + (lane & 3) * 2;
        bv[n][0] = brel[col];
        bv[n][1] = brel[col + 1];
    }
#pragma unroll
    for (int m = 0; m < 4; m++) {
        const int grow0 = cta * M_CTA + wm * 64 + m * 16 + (lane >> 2);
        const int grow1 = grow0 + 8;
#pragma unroll
        for (int n = 0; n < 4; n++) {
            const int col = wn * 32 + n * 8 + (lane & 3) * 2;
            if (grow0 < N_NODES) {
                float2 v = make_float2(acc[m][n][0] + bv[n][0],
                                       acc[m][n][1] + bv[n][1]);
                *(float2*)(out + (size_t)grow0 * C + col) = v;
            }
            if (grow1 < N_NODES) {
                float2 v = make_float2(acc[m][n][2] + bv[n][0],
                                       acc[m][n][3] + bv[n][1]);
                *(float2*)(out + (size_t)grow1 * C + col) = v;
            }
        }
    }
}

// ===========================================================================
// inputs (metadata order): x, edge_index, edge_weights, W_rel, b_rel, W_root
// ===========================================================================
extern "C" void kernel_launch(void* const* d_in, const int* in_sizes, int n_in,
                              void* d_out, int out_size) {
    const float* x     = (const float*)d_in[0];
    const float* ew    = (const float*)d_in[2];
    const float* Wrel  = (const float*)d_in[3];
    const float* brel  = (const float*)d_in[4];
    const float* Wroot = (const float*)d_in[5];
    float* out = (float*)d_out;

    cudaFuncSetAttribute(gemm_tf32, cudaFuncAttributeMaxDynamicSharedMemorySize,
                         SMEM_BYTES);

    agg_kernel<<<N_GRAPHS, 128>>>(x, ew);
    gemm_tf32<<<GRID2, 256, SMEM_BYTES>>>(x, Wrel, brel, Wroot, out);
}

// round 9
// speedup vs baseline: 1.2938x; 1.0969x over previous
#include <cuda_runtime.h>
#include <cstdint>

#define N_EL   19
#define GPC    8                    // graphs per CTA
#define ROWS   (N_EL * GPC)         // 152 valid rows per CTA
#define MPAD   160                  // padded to 10 m16 tiles
#define N_GRAPHS 1800
#define N_NODES  (N_GRAPHS * N_EL)  // 34200
#define C      128
#define GRID   (N_GRAPHS / GPC)     // 225 exact

// smem map (bytes from dynamic base)
#define BOFF   0                    // B tf32: 4 k32-chunks x 256 rows x 128B
#define BCH    32768
#define XOFF   131072               // X tf32: 4 chunks x 160 rows x 128B
#define XCH    20480
#define POFF   131072               // P fp32 (reuses X after MMA): 152 x 528B
#define QOFF   0                    // Q fp32 (reuses B): 152 x 528B
#define PQSTR  528                  // 132-word row stride (conflict relief)
#define AOFF   212992               // A 19x20 fp32
#define SMEM_BYTES 214528

// ===========================================================================
// helpers
// ===========================================================================
__device__ __forceinline__ uint32_t s2u(const void* p) {
    uint32_t a;
    asm("{ .reg .u64 t; cvta.to.shared.u64 t, %1; cvt.u32.u64 %0, t; }"
        : "=r"(a) : "l"(p));
    return a;
}
__device__ __forceinline__ uint32_t t32(float f) {
    uint32_t u;
    asm("cvt.rna.tf32.f32 %0, %1;" : "=r"(u) : "f"(f));
    return u;
}
__device__ __forceinline__ void sts16(uint32_t addr, uint4 v) {
    asm volatile("st.shared.v4.b32 [%0], {%1,%2,%3,%4};"
                 :: "r"(addr), "r"(v.x), "r"(v.y), "r"(v.z), "r"(v.w) : "memory");
}
__device__ __forceinline__ void sts8f(uint32_t addr, float a, float b) {
    asm volatile("st.shared.v2.f32 [%0], {%1,%2};"
                 :: "r"(addr), "f"(a), "f"(b) : "memory");
}
__device__ __forceinline__ uint4 lds16(uint32_t addr) {
    uint4 v;
    asm volatile("ld.shared.v4.b32 {%0,%1,%2,%3}, [%4];"
                 : "=r"(v.x), "=r"(v.y), "=r"(v.z), "=r"(v.w) : "r"(addr));
    return v;
}
__device__ __forceinline__ float4 lds16f(uint32_t addr) {
    float4 v;
    asm volatile("ld.shared.v4.f32 {%0,%1,%2,%3}, [%4];"
                 : "=f"(v.x), "=f"(v.y), "=f"(v.z), "=f"(v.w) : "r"(addr));
    return v;
}
__device__ __forceinline__ void mma_tf32(float* d, uint32_t a0, uint32_t a1,
                                         uint32_t a2, uint32_t a3,
                                         uint32_t b0, uint32_t b1) {
    asm volatile(
        "mma.sync.aligned.m16n8k8.row.col.f32.tf32.tf32.f32 "
        "{%0,%1,%2,%3}, {%4,%5,%6,%7}, {%8,%9}, {%0,%1,%2,%3};"
        : "+f"(d[0]), "+f"(d[1]), "+f"(d[2]), "+f"(d[3])
        : "r"(a0), "r"(a1), "r"(a2), "r"(a3), "r"(b0), "r"(b1));
}
// stage 16 consecutive k-values (k16 half 'h' of a k32 chunk) of one row into
// the interleaved+XOR-swizzled layout: word(k) = (k&3)*8 + (k>>2), granule
// g stored at g ^ (row & 7).
__device__ __forceinline__ void stage16(uint32_t rowbase, int row, int h,
                                        const float* f) {
#pragma unroll
    for (int cc = 0; cc < 4; cc++) {
        uint4 v = make_uint4(t32(f[cc]), t32(f[cc + 4]),
                             t32(f[cc + 8]), t32(f[cc + 12]));
        sts16(rowbase + (uint32_t)(((cc * 2 + h) ^ (row & 7)) << 4), v);
    }
}

// ===========================================================================
// Fused kernel:
//   per CTA (8 graphs): [P|Q] = X(152x128) @ [Wrel|Wroot]^T  (tf32 MMA)
//   then out = A @ P_g + Q_g + b  (fp32, per graph, A shared 19x19 from ew)
// 256 threads: 8 warps (wm 0..1 x wn 0..3), warp tile m80 x n64.
// ===========================================================================
__global__ __launch_bounds__(256, 1) void fused_kernel(
        const float* __restrict__ x,
        const float* __restrict__ ew,
        const float* __restrict__ Wrel,
        const float* __restrict__ brel,
        const float* __restrict__ Wroot,
        float* __restrict__ out) {
    extern __shared__ __align__(16) char smem[];
    const uint32_t sb = s2u(smem);
    float* As = (float*)(smem + AOFF);

    const int tid  = threadIdx.x;
    const int wid  = tid >> 5;
    const int lane = tid & 31;
    const int cta  = blockIdx.x;

    // ---- build A (19x19, shared by all graphs) from edge weights
    for (int e = tid; e < N_EL * N_EL; e += 256) {
        const int j = e / N_EL, i = e % N_EL;
        float w = 0.0f;
        if (i != j) {
            const int r = (j < i) ? j : (j - 1);
            w = ew[i * (N_EL - 1) + r];
        }
        As[j * 20 + i] = w;
    }

    // ---- stage X: 1280 units (row 0..159, chunk 0..3, half 0..1)
    for (int u = tid; u < MPAD * 8; u += 256) {
        const int row = u >> 3, c = (u >> 1) & 3, h = u & 1;
        float f[16];
        if (row < ROWS) {
            const float4* s4 = (const float4*)(x + (size_t)(cta * ROWS + row) * C
                                               + c * 32 + h * 16);
            *(float4*)&f[0]  = s4[0];
            *(float4*)&f[4]  = s4[1];
            *(float4*)&f[8]  = s4[2];
            *(float4*)&f[12] = s4[3];
        } else {
#pragma unroll
            for (int q = 0; q < 16; q++) f[q] = 0.0f;
        }
        stage16(sb + XOFF + (uint32_t)c * XCH + (uint32_t)row * 128u, row, h, f);
    }

    // ---- stage B = [Wrel; Wroot]: 2048 units (n 0..255, chunk, half)
    for (int u = tid; u < 256 * 8; u += 256) {
        const int n = u >> 3, c = (u >> 1) & 3, h = u & 1;
        const float* src = (n < 128) ? Wrel + (size_t)n * C
                                     : Wroot + (size_t)(n - 128) * C;
        const float4* s4 = (const float4*)(src + c * 32 + h * 16);
        float f[16];
        *(float4*)&f[0]  = s4[0];
        *(float4*)&f[4]  = s4[1];
        *(float4*)&f[8]  = s4[2];
        *(float4*)&f[12] = s4[3];
        stage16(sb + BOFF + (uint32_t)c * BCH + (uint32_t)n * 128u, n, h, f);
    }
    __syncthreads();

    // ---- MMA burst: warp tile m80 x n64, K=128
    const int fr = lane >> 2;
    const int fc = lane & 3;
    const int wm = wid >> 2;        // 0..1
    const int wn = wid & 3;         // 0..3

    float acc[5][8][4];
#pragma unroll
    for (int mt = 0; mt < 5; mt++)
#pragma unroll
        for (int n8 = 0; n8 < 8; n8++)
#pragma unroll
            for (int q = 0; q < 4; q++)
                acc[mt][n8][q] = 0.0f;

#pragma unroll
    for (int c = 0; c < 4; c++) {
#pragma unroll
        for (int s = 0; s < 2; s++) {
            uint4 bf[8];
#pragma unroll
            for (int n8 = 0; n8 < 8; n8++) {
                const int nr = wn * 64 + n8 * 8 + fr;
                bf[n8] = lds16(sb + BOFF + (uint32_t)c * BCH + (uint32_t)nr * 128u
                               + (uint32_t)(((fc * 2 + s) ^ (nr & 7)) << 4));
            }
#pragma unroll
            for (int mt = 0; mt < 5; mt++) {
                const int r0 = wm * 80 + mt * 16 + fr;
                const uint32_t xb = sb + XOFF + (uint32_t)c * XCH
                                  + (uint32_t)(((fc * 2 + s) ^ (r0 & 7)) << 4);
                uint4 lo = lds16(xb + (uint32_t)r0 * 128u);
                uint4 hi = lds16(xb + (uint32_t)(r0 + 8) * 128u);
#pragma unroll
                for (int n8 = 0; n8 < 8; n8++) {
                    mma_tf32(acc[mt][n8], lo.x, hi.x, lo.y, hi.y,
                             bf[n8].x, bf[n8].y);
                    mma_tf32(acc[mt][n8], lo.z, hi.z, lo.w, hi.w,
                             bf[n8].z, bf[n8].w);
                }
            }
        }
    }
    __syncthreads();   // X/B smem reads complete -> safe to overwrite with P/Q

    // ---- write accumulators to P (cols 0..127) / Q (cols 128..255)
#pragma unroll
    for (int mt = 0; mt < 5; mt++) {
#pragma unroll
        for (int n8 = 0; n8 < 8; n8++) {
            const int col = wn * 64 + n8 * 8 + fc * 2;
            const uint32_t base = (col < 128)
                ? sb + POFF + (uint32_t)col * 4u
                : sb + QOFF + (uint32_t)(col - 128) * 4u;
#pragma unroll
            for (int half = 0; half < 2; half++) {
                const int r = wm * 80 + mt * 16 + fr + half * 8;
                if (r < ROWS)
                    sts8f(base + (uint32_t)r * PQSTR,
                          acc[mt][n8][half * 2], acc[mt][n8][half * 2 + 1]);
            }
        }
    }
    __syncthreads();

    // ---- phase 2: warp g handles graph g; lane owns 4 cols
    {
        const int g = wid;                       // 0..7
        const float4 bv = *(const float4*)(brel + lane * 4);
        float4 p[N_EL];
#pragma unroll
        for (int i = 0; i < N_EL; i++)
            p[i] = lds16f(sb + POFF + (uint32_t)(g * N_EL + i) * PQSTR
                          + (uint32_t)lane * 16u);
#pragma unroll
        for (int j = 0; j < N_EL; j++) {
            float4 o = lds16f(sb + QOFF + (uint32_t)(g * N_EL + j) * PQSTR
                              + (uint32_t)lane * 16u);
            o.x += bv.x; o.y += bv.y; o.z += bv.z; o.w += bv.w;
#pragma unroll
            for (int i = 0; i < N_EL; i++) {
                const float a = As[j * 20 + i];
                o.x = fmaf(a, p[i].x, o.x);
                o.y = fmaf(a, p[i].y, o.y);
                o.z = fmaf(a, p[i].z, o.z);
                o.w = fmaf(a, p[i].w, o.w);
            }
            *(float4*)(out + (size_t)(cta * ROWS + g * N_EL + j) * C
                       + lane * 4) = o;
        }
    }
}

// ===========================================================================
// inputs (metadata order): x, edge_index, edge_weights, W_rel, b_rel, W_root
// ===========================================================================
extern "C" void kernel_launch(void* const* d_in, const int* in_sizes, int n_in,
                              void* d_out, int out_size) {
    const float* x     = (const float*)d_in[0];
    const float* ew    = (const float*)d_in[2];
    const float* Wrel  = (const float*)d_in[3];
    const float* brel  = (const float*)d_in[4];
    const float* Wroot = (const float*)d_in[5];
    float* out = (float*)d_out;

    cudaFuncSetAttribute(fused_kernel, cudaFuncAttributeMaxDynamicSharedMemorySize,
                         SMEM_BYTES);

    fused_kernel<<<GRID, 256, SMEM_BYTES>>>(x, ew, Wrel, brel, Wroot, out);
}